// round 7
// baseline (speedup 1.0000x reference)
#include <cuda_runtime.h>
#include <cuda_bf16.h>
#include <cstdint>
#include <cstddef>

// Problem constants
#define BB   256
#define TT   1024
#define FF   64
#define HH   128
#define GG   512   // 4*H

using u64 = unsigned long long;

// ---------------------------------------------------------------------------
// Packed f32x2 helpers
// ---------------------------------------------------------------------------
__device__ __forceinline__ u64 ffma2(u64 a, u64 b, u64 c) {
    u64 d;
    asm("fma.rn.f32x2 %0, %1, %2, %3;" : "=l"(d) : "l"(a), "l"(b), "l"(c));
    return d;
}
__device__ __forceinline__ u64 pk(float x, float y) {
    u64 d; asm("mov.b64 %0, {%1, %2};" : "=l"(d) : "f"(x), "f"(y)); return d;
}
__device__ __forceinline__ float2 upk(u64 v) {
    float2 r; asm("mov.b64 {%0, %1}, %2;" : "=f"(r.x), "=f"(r.y) : "l"(v)); return r;
}

// ---------------------------------------------------------------------------
// Scratch (device globals; allocation in kernel_launch is forbidden)
// ---------------------------------------------------------------------------
__device__ float g_xg[(size_t)BB * TT * GG];   // 512 MB gate preactivations
__device__ float g_hs[(size_t)BB * TT * HH];   // 128 MB hidden states

// ---------------------------------------------------------------------------
// K1:  xg = x @ W_ih^T + (b_ih + b_hh)
//   Tile: 32 bt-rows x 128 gates, 256 threads. lane = row, warp = 16 gates.
//   x row held in 64 registers (no smem staging); weights broadcast LDS.128.
// ---------------------------------------------------------------------------
__global__ __launch_bounds__(256) void k1_xgemm(
    const float* __restrict__ x,
    const float* __restrict__ Wih,
    const float* __restrict__ bih,
    const float* __restrict__ bhh)
{
    __shared__ __align__(16) float ws[64][128];   // [k][gate], 32 KB

    const int bt0  = blockIdx.x * 32;
    const int g0   = blockIdx.y * 128;
    const int t    = threadIdx.x;
    const int lane = t & 31;          // row within tile
    const int wid  = t >> 5;          // 0..7 -> gate group
    const int gloc = wid * 16;        // local gate base

    // load W tile transposed (128 gates x 64 k)
    for (int i = t; i < 2048; i += 256) {
        int g  = i >> 4;
        int kq = i & 15;
        float4 v = ((const float4*)(Wih + (size_t)(g0 + g) * FF))[kq];
        int k = kq * 4;
        ws[k + 0][g] = v.x;
        ws[k + 1][g] = v.y;
        ws[k + 2][g] = v.z;
        ws[k + 3][g] = v.w;
    }

    // my x row into registers (16 LDG.128)
    float xr[64];
    {
        const float4* xp = (const float4*)(x + (size_t)(bt0 + lane) * FF);
#pragma unroll
        for (int q = 0; q < 16; q++) {
            float4 v = xp[q];
            xr[4 * q + 0] = v.x;
            xr[4 * q + 1] = v.y;
            xr[4 * q + 2] = v.z;
            xr[4 * q + 3] = v.w;
        }
    }

    // init accumulators with bias (8 packed pairs = 16 gates)
    u64 acc[8];
#pragma unroll
    for (int p = 0; p < 8; p++) {
        int g = g0 + gloc + 2 * p;
        acc[p] = pk(bih[g] + bhh[g], bih[g + 1] + bhh[g + 1]);
    }
    __syncthreads();

#pragma unroll 8
    for (int k = 0; k < 64; k++) {
        u64 xx = pk(xr[k], xr[k]);
        ulonglong2 wa = *(const ulonglong2*)&ws[k][gloc];
        ulonglong2 wb = *(const ulonglong2*)&ws[k][gloc + 4];
        ulonglong2 wc = *(const ulonglong2*)&ws[k][gloc + 8];
        ulonglong2 wd = *(const ulonglong2*)&ws[k][gloc + 12];
        acc[0] = ffma2(xx, wa.x, acc[0]);  acc[1] = ffma2(xx, wa.y, acc[1]);
        acc[2] = ffma2(xx, wb.x, acc[2]);  acc[3] = ffma2(xx, wb.y, acc[3]);
        acc[4] = ffma2(xx, wc.x, acc[4]);  acc[5] = ffma2(xx, wc.y, acc[5]);
        acc[6] = ffma2(xx, wd.x, acc[6]);  acc[7] = ffma2(xx, wd.y, acc[7]);
    }

    // store 16 gates (4 float4), 64B contiguous per lane
    float* outp = g_xg + (size_t)(bt0 + lane) * GG + g0 + gloc;
#pragma unroll
    for (int q = 0; q < 4; q++) {
        float2 lo = upk(acc[2 * q]);
        float2 hi = upk(acc[2 * q + 1]);
        *(float4*)(outp + q * 4) = make_float4(lo.x, lo.y, hi.x, hi.y);
    }
}

// ---------------------------------------------------------------------------
// K2: persistent LSTM recurrence, 64 clusters x 2 CTAs.
//   Per-step cross-CTA handshake via parity mbarriers (no barrier.cluster,
//   no per-step L1D flush). Producer: st.shared::cluster + arrive.release.
//   Consumer: try_wait.parity.acquire.cluster on local mbar.
// ---------------------------------------------------------------------------
__device__ __forceinline__ float fsigm(float v) {
    return __fdividef(1.0f, 1.0f + __expf(-v));
}
__device__ __forceinline__ float ftanh(float v) {
    return 1.0f - __fdividef(2.0f, 1.0f + __expf(2.0f * v));
}

__device__ __forceinline__ void mbar_wait_cluster(uint32_t addr, uint32_t phase) {
    asm volatile(
        "{\n\t"
        ".reg .pred P;\n\t"
        "LAB_WAIT_%=:\n\t"
        "mbarrier.try_wait.parity.acquire.cluster.shared::cta.b64 P, [%0], %1, 0x989680;\n\t"
        "@P bra LAB_DONE_%=;\n\t"
        "bra LAB_WAIT_%=;\n\t"
        "LAB_DONE_%=:\n\t"
        "}"
        :: "r"(addr), "r"(phase) : "memory");
}

__global__ __launch_bounds__(512, 1) __cluster_dims__(2, 1, 1)
void k2_lstm(const float* __restrict__ Whh)
{
    __shared__ __align__(16) float hbuf[4][68];            // [row][k] padded
    __shared__ __align__(16) float pbuf[2][2][4][64][4];   // [parity][src][gt][j][row]
    __shared__ __align__(8)  unsigned long long mbar[2];   // parity mbarriers

    const int t    = threadIdx.x;          // == global gate index
    const int rank = blockIdx.x & 1;
    const int cid  = blockIdx.x >> 1;
    const int rowBase = cid * 4;
    const int kOff = rank * 64;

    // --- load my W_hh row-half into 32 packed register pairs ---
    u64 w2[32];
    {
        const ulonglong2* wp = (const ulonglong2*)(Whh + (size_t)t * HH + kOff);
#pragma unroll
        for (int q = 0; q < 16; q++) {
            ulonglong2 v = wp[q];
            w2[2 * q]     = v.x;
            w2[2 * q + 1] = v.y;
        }
    }

    // gate decomposition for partial routing
    const int gt    = t >> 7;        // gate type 0..3 (i,f,g,o)
    const int jg    = t & 127;       // h column of this gate
    const int owner = jg >> 6;       // owning CTA of that h column
    const int jl    = jg & 63;       // column local to owner
    const bool remote = (owner != rank);

    float* localDst = &pbuf[0][rank][gt][jl][0];
    const uint32_t mbarLoc0 = (uint32_t)__cvta_generic_to_shared(&mbar[0]);
    const uint32_t mbarLoc1 = (uint32_t)__cvta_generic_to_shared(&mbar[1]);
    uint32_t remoteAddr = 0, peerMbar0 = 0, peerMbar1 = 0;
    if (remote) {
        uint32_t la = (uint32_t)__cvta_generic_to_shared(localDst);
        asm volatile("mapa.shared::cluster.u32 %0, %1, %2;"
                     : "=r"(remoteAddr) : "r"(la), "r"(owner));
        asm volatile("mapa.shared::cluster.u32 %0, %1, %2;"
                     : "=r"(peerMbar0) : "r"(mbarLoc0), "r"(owner));
        asm volatile("mapa.shared::cluster.u32 %0, %1, %2;"
                     : "=r"(peerMbar1) : "r"(mbarLoc1), "r"(owner));
    }
    const uint32_t PAR_STRIDE = 2u * 4u * 64u * 4u * 4u;   // 8192 bytes

    // pointwise identity (first 256 threads): thread = (j, row)
    const int pj = t >> 2;
    const int pr = t & 3;
    const int pb = rowBase + pr;

    // init: mbarriers expect 256 arrivals (one per remote producer thread)
    if (t == 0) {
        asm volatile("mbarrier.init.shared.b64 [%0], %1;" :: "r"(mbarLoc0), "r"(256) : "memory");
        asm volatile("mbarrier.init.shared.b64 [%0], %1;" :: "r"(mbarLoc1), "r"(256) : "memory");
    }
    if (t < 256) hbuf[pr][pj] = 0.0f;
    float c = 0.0f;
    __syncthreads();
    // cluster-wide: mbarriers + hbuf init visible before any remote traffic
    asm volatile("barrier.cluster.arrive.aligned;" ::: "memory");
    asm volatile("barrier.cluster.wait.aligned;"   ::: "memory");

    for (int step = 0; step < TT; step++) {
        const int par = step & 1;
        const uint32_t ph = (uint32_t)((step >> 1) & 1);

        // prefetch xg for my 4 owned gates (hidden under phase A)
        float xg0 = 0.f, xg1 = 0.f, xg2 = 0.f, xg3 = 0.f;
        if (t < 256) {
            size_t base = ((size_t)pb * TT + step) * GG + (size_t)(rank * 64 + pj);
            xg0 = g_xg[base];
            xg1 = g_xg[base + 128];
            xg2 = g_xg[base + 256];
            xg3 = g_xg[base + 384];
        }

        // --- phase A: packed split-K dot products (4 rows per thread) ---
        u64 a0 = 0, a1 = 0, a2 = 0, a3 = 0;
#pragma unroll
        for (int kq = 0; kq < 16; kq++) {
            ulonglong2 h0 = *(const ulonglong2*)&hbuf[0][kq * 4];
            ulonglong2 h1 = *(const ulonglong2*)&hbuf[1][kq * 4];
            ulonglong2 h2 = *(const ulonglong2*)&hbuf[2][kq * 4];
            ulonglong2 h3 = *(const ulonglong2*)&hbuf[3][kq * 4];
            u64 wa = w2[2 * kq], wb = w2[2 * kq + 1];
            a0 = ffma2(wa, h0.x, a0);  a0 = ffma2(wb, h0.y, a0);
            a1 = ffma2(wa, h1.x, a1);  a1 = ffma2(wb, h1.y, a1);
            a2 = ffma2(wa, h2.x, a2);  a2 = ffma2(wb, h2.y, a2);
            a3 = ffma2(wa, h3.x, a3);  a3 = ffma2(wb, h3.y, a3);
        }
        float2 s0 = upk(a0), s1 = upk(a1), s2 = upk(a2), s3 = upk(a3);
        float ax = s0.x + s0.y;
        float ay = s1.x + s1.y;
        float az = s2.x + s2.y;
        float aw = s3.x + s3.y;

        // --- route partials to the owning CTA ---
        if (!remote) {
            *(float4*)((char*)localDst + par * PAR_STRIDE) =
                make_float4(ax, ay, az, aw);
        } else {
            uint32_t a = remoteAddr + par * PAR_STRIDE;
            asm volatile("st.shared::cluster.f32 [%0], %1;" :: "r"(a),      "f"(ax) : "memory");
            asm volatile("st.shared::cluster.f32 [%0], %1;" :: "r"(a + 4),  "f"(ay) : "memory");
            asm volatile("st.shared::cluster.f32 [%0], %1;" :: "r"(a + 8),  "f"(az) : "memory");
            asm volatile("st.shared::cluster.f32 [%0], %1;" :: "r"(a + 12), "f"(aw) : "memory");
            uint32_t mb = par ? peerMbar1 : peerMbar0;
            asm volatile("mbarrier.arrive.release.cluster.shared::cluster.b64 _, [%0];"
                         :: "r"(mb) : "memory");
        }

        __syncthreads();   // local partials visible within CTA

        // --- pointwise LSTM update for my owned (row, column) ---
        if (t < 256) {
            mbar_wait_cluster(par ? mbarLoc1 : mbarLoc0, ph);  // peer partials

            float gi = xg0 + pbuf[par][0][0][pj][pr] + pbuf[par][1][0][pj][pr];
            float gf = xg1 + pbuf[par][0][1][pj][pr] + pbuf[par][1][1][pj][pr];
            float gc = xg2 + pbuf[par][0][2][pj][pr] + pbuf[par][1][2][pj][pr];
            float go = xg3 + pbuf[par][0][3][pj][pr] + pbuf[par][1][3][pj][pr];

            float iv = fsigm(gi);
            float fv = fsigm(gf);
            float gv = ftanh(gc);
            float ov = fsigm(go);

            c = fv * c + iv * gv;
            float h = ov * ftanh(c);

            hbuf[pr][pj] = h;
            g_hs[((size_t)pb * TT + step) * HH + (size_t)(rank * 64 + pj)] = h;
        }
        __syncthreads();   // h visible to all 512 threads before next phase A
    }

    // teardown safety: no CTA exits while peer traffic could be in flight
    asm volatile("barrier.cluster.arrive.aligned;" ::: "memory");
    asm volatile("barrier.cluster.wait.aligned;"   ::: "memory");
}

// ---------------------------------------------------------------------------
// K3: out = hs @ W_out^T.  hs: [BT, 128], W_out: [64, 128].
//   lane = row (32 rows/block), warp = 8 f-columns. hs row in registers
//   (two 64-reg chunks); W_out broadcast from smem.
// ---------------------------------------------------------------------------
__global__ __launch_bounds__(256) void k3_proj(
    const float* __restrict__ Wout,
    float* __restrict__ out)
{
    __shared__ __align__(16) float ws[128][64];     // [k][f], 32 KB

    const int bt0  = blockIdx.x * 32;
    const int t    = threadIdx.x;
    const int lane = t & 31;
    const int wid  = t >> 5;
    const int f0   = wid * 8;

    // load W_out transposed: 64 f x 128 k
    for (int i = t; i < 2048; i += 256) {
        int f  = i >> 5;
        int kq = i & 31;
        float4 v = ((const float4*)(Wout + (size_t)f * HH))[kq];
        int k = kq * 4;
        ws[k + 0][f] = v.x;
        ws[k + 1][f] = v.y;
        ws[k + 2][f] = v.z;
        ws[k + 3][f] = v.w;
    }

    const float4* hp = (const float4*)(g_hs + (size_t)(bt0 + lane) * HH);

    u64 acc[4] = {0, 0, 0, 0};

    // chunk 0: k = 0..63
    float hr[64];
#pragma unroll
    for (int q = 0; q < 16; q++) {
        float4 v = hp[q];
        hr[4 * q + 0] = v.x; hr[4 * q + 1] = v.y;
        hr[4 * q + 2] = v.z; hr[4 * q + 3] = v.w;
    }
    __syncthreads();

#pragma unroll 8
    for (int k = 0; k < 64; k++) {
        u64 xx = pk(hr[k], hr[k]);
        ulonglong2 wa = *(const ulonglong2*)&ws[k][f0];
        ulonglong2 wb = *(const ulonglong2*)&ws[k][f0 + 4];
        acc[0] = ffma2(xx, wa.x, acc[0]);  acc[1] = ffma2(xx, wa.y, acc[1]);
        acc[2] = ffma2(xx, wb.x, acc[2]);  acc[3] = ffma2(xx, wb.y, acc[3]);
    }

    // chunk 1: k = 64..127
#pragma unroll
    for (int q = 0; q < 16; q++) {
        float4 v = hp[16 + q];
        hr[4 * q + 0] = v.x; hr[4 * q + 1] = v.y;
        hr[4 * q + 2] = v.z; hr[4 * q + 3] = v.w;
    }
#pragma unroll 8
    for (int k = 0; k < 64; k++) {
        u64 xx = pk(hr[k], hr[k]);
        ulonglong2 wa = *(const ulonglong2*)&ws[64 + k][f0];
        ulonglong2 wb = *(const ulonglong2*)&ws[64 + k][f0 + 4];
        acc[0] = ffma2(xx, wa.x, acc[0]);  acc[1] = ffma2(xx, wa.y, acc[1]);
        acc[2] = ffma2(xx, wb.x, acc[2]);  acc[3] = ffma2(xx, wb.y, acc[3]);
    }

    float2 a0 = upk(acc[0]), a1 = upk(acc[1]), a2 = upk(acc[2]), a3 = upk(acc[3]);
    float* op = out + (size_t)(bt0 + lane) * FF + f0;
    *(float4*)op       = make_float4(a0.x, a0.y, a1.x, a1.y);
    *(float4*)(op + 4) = make_float4(a2.x, a2.y, a3.x, a3.y);
}

// ---------------------------------------------------------------------------
// launch
// ---------------------------------------------------------------------------
extern "C" void kernel_launch(void* const* d_in, const int* in_sizes, int n_in,
                              void* d_out, int out_size)
{
    const float* x    = (const float*)d_in[0];  // [256,1024,64]
    const float* Wih  = (const float*)d_in[1];  // [512,64]
    const float* Whh  = (const float*)d_in[2];  // [512,128]
    const float* bih  = (const float*)d_in[3];  // [512]
    const float* bhh  = (const float*)d_in[4];  // [512]
    const float* Wout = (const float*)d_in[5];  // [64,128]
    float* out = (float*)d_out;                 // [256,1024,64]

    (void)in_sizes; (void)n_in; (void)out_size;

    k1_xgemm<<<dim3((BB * TT) / 32, 4), 256>>>(x, Wih, bih, bhh);
    k2_lstm<<<128, 512>>>(Whh);
    k3_proj<<<(BB * TT) / 32, 256>>>(Wout, out);
}

// round 8
// speedup vs baseline: 1.2062x; 1.2062x over previous
#include <cuda_runtime.h>
#include <cuda_bf16.h>
#include <cstdint>
#include <cstddef>

// Problem constants
#define BB   256
#define TT   1024
#define FF   64
#define HH   128
#define GG   512   // 4*H

// ---------------------------------------------------------------------------
// Scratch (device globals; allocation in kernel_launch is forbidden)
// ---------------------------------------------------------------------------
__device__ float g_xg[(size_t)BB * TT * GG];   // 512 MB gate preactivations
__device__ float g_hs[(size_t)BB * TT * HH];   // 128 MB hidden states

// ---------------------------------------------------------------------------
// K1:  xg = x @ W_ih^T + (b_ih + b_hh)
//   Tile: 32 bt-rows x 128 gates, 256 threads. lane = row, warp = 16 gates.
//   Weights broadcast LDS.128 (warp-uniform address, 1 wavefront each);
//   x staged coalesced in smem, row stride 65 -> conflict-free LDS.32.
//   Scalar FFMA only (f32x2 proven not to pay on sm_100a).
// ---------------------------------------------------------------------------
__global__ __launch_bounds__(256) void k1_xgemm(
    const float* __restrict__ x,
    const float* __restrict__ Wih,
    const float* __restrict__ bih,
    const float* __restrict__ bhh)
{
    __shared__ float xs[32][65];                  // bank = (lane + k) % 32
    __shared__ __align__(16) float ws[64][128];   // [k][gate], 32 KB

    const int bt0  = blockIdx.x * 32;
    const int g0   = blockIdx.y * 128;
    const int t    = threadIdx.x;
    const int lane = t & 31;          // row within tile
    const int wid  = t >> 5;          // 0..7 -> gate group
    const int gloc = wid * 16;        // local gate base (warp-uniform)

    // load x tile coalesced (32 rows x 64 k = 512 float4)
    for (int i = t; i < 512; i += 256) {
        int row = i >> 4;
        int kq  = i & 15;
        float4 v = ((const float4*)(x + (size_t)(bt0 + row) * FF))[kq];
        xs[row][kq * 4 + 0] = v.x;
        xs[row][kq * 4 + 1] = v.y;
        xs[row][kq * 4 + 2] = v.z;
        xs[row][kq * 4 + 3] = v.w;
    }
    // load W tile transposed (128 gates x 64 k)
    for (int i = t; i < 2048; i += 256) {
        int g  = i >> 4;
        int kq = i & 15;
        float4 v = ((const float4*)(Wih + (size_t)(g0 + g) * FF))[kq];
        int k = kq * 4;
        ws[k + 0][g] = v.x;
        ws[k + 1][g] = v.y;
        ws[k + 2][g] = v.z;
        ws[k + 3][g] = v.w;
    }

    // bias for my 16 gates (broadcast LDG, cached)
    float4 acc0, acc1, acc2, acc3;
    {
        const float4* b1 = (const float4*)(bih + g0 + gloc);
        const float4* b2 = (const float4*)(bhh + g0 + gloc);
        float4 u, v;
        u = b1[0]; v = b2[0]; acc0 = make_float4(u.x+v.x, u.y+v.y, u.z+v.z, u.w+v.w);
        u = b1[1]; v = b2[1]; acc1 = make_float4(u.x+v.x, u.y+v.y, u.z+v.z, u.w+v.w);
        u = b1[2]; v = b2[2]; acc2 = make_float4(u.x+v.x, u.y+v.y, u.z+v.z, u.w+v.w);
        u = b1[3]; v = b2[3]; acc3 = make_float4(u.x+v.x, u.y+v.y, u.z+v.z, u.w+v.w);
    }
    __syncthreads();

#pragma unroll 8
    for (int k = 0; k < 64; k++) {
        float xv = xs[lane][k];                      // conflict-free LDS.32
        float4 wa = *(const float4*)&ws[k][gloc];      // broadcast LDS.128
        float4 wb = *(const float4*)&ws[k][gloc + 4];
        float4 wc = *(const float4*)&ws[k][gloc + 8];
        float4 wd = *(const float4*)&ws[k][gloc + 12];
        acc0.x += xv * wa.x; acc0.y += xv * wa.y; acc0.z += xv * wa.z; acc0.w += xv * wa.w;
        acc1.x += xv * wb.x; acc1.y += xv * wb.y; acc1.z += xv * wb.z; acc1.w += xv * wb.w;
        acc2.x += xv * wc.x; acc2.y += xv * wc.y; acc2.z += xv * wc.z; acc2.w += xv * wc.w;
        acc3.x += xv * wd.x; acc3.y += xv * wd.y; acc3.z += xv * wd.z; acc3.w += xv * wd.w;
    }

    // store 16 contiguous gates (4x STG.128, full-sector writes)
    float* outp = g_xg + (size_t)(bt0 + lane) * GG + g0 + gloc;
    *(float4*)(outp + 0)  = acc0;
    *(float4*)(outp + 4)  = acc1;
    *(float4*)(outp + 8)  = acc2;
    *(float4*)(outp + 12) = acc3;
}

// ---------------------------------------------------------------------------
// K2: persistent LSTM recurrence (R3 structure: 64 clusters x 2 CTAs,
//   scalar FFMA phase A, barrier.cluster) + fast MUFU pointwise
//   (accuracy proven in R6/R7: rel_err 4.25e-7).
// ---------------------------------------------------------------------------
__device__ __forceinline__ float fsigm(float v) {
    return __fdividef(1.0f, 1.0f + __expf(-v));
}
__device__ __forceinline__ float ftanh(float v) {
    // saturation-safe: no inf/inf
    return 1.0f - __fdividef(2.0f, 1.0f + __expf(2.0f * v));
}

__global__ __launch_bounds__(512, 1) __cluster_dims__(2, 1, 1)
void k2_lstm(const float* __restrict__ Whh)
{
    __shared__ __align__(16) float hbuf[64][4];            // my h-half, [kLocal][row]
    __shared__ __align__(16) float pbuf[2][2][4][64][4];   // [parity][src][gt][j][row]

    const int t    = threadIdx.x;          // == global gate index
    const int rank = blockIdx.x & 1;
    const int cid  = blockIdx.x >> 1;
    const int rowBase = cid * 4;
    const int kOff = rank * 64;

    // --- load my W_hh row-half into registers ---
    float w[64];
    {
        const float4* wp = (const float4*)(Whh + (size_t)t * HH + kOff);
#pragma unroll
        for (int q = 0; q < 16; q++) {
            float4 v = wp[q];
            w[4 * q + 0] = v.x;
            w[4 * q + 1] = v.y;
            w[4 * q + 2] = v.z;
            w[4 * q + 3] = v.w;
        }
    }

    // gate decomposition for partial routing
    const int gt    = t >> 7;        // gate type 0..3 (i,f,g,o)
    const int jg    = t & 127;       // h column of this gate
    const int owner = jg >> 6;       // owning CTA of that h column
    const int jl    = jg & 63;       // column local to owner
    const bool remote = (owner != rank);

    float* localDst = &pbuf[0][rank][gt][jl][0];
    uint32_t remoteAddr = 0;
    if (remote) {
        uint32_t la = (uint32_t)__cvta_generic_to_shared(localDst);
        asm volatile("mapa.shared::cluster.u32 %0, %1, %2;"
                     : "=r"(remoteAddr) : "r"(la), "r"(owner));
    }
    const uint32_t PAR_STRIDE = 2u * 4u * 64u * 4u * 4u;   // 8192 bytes

    // pointwise identity (first 256 threads): thread = (j, row)
    const int pj = t >> 2;
    const int pr = t & 3;
    const int pb = rowBase + pr;

    if (t < 256) hbuf[pj][pr] = 0.0f;
    float c = 0.0f;
    __syncthreads();

    const float4* h4 = (const float4*)hbuf;

    for (int step = 0; step < TT; step++) {
        const int par = step & 1;

        // prefetch this step's xg for my 4 owned gates (hidden under phase A)
        float xg0 = 0.f, xg1 = 0.f, xg2 = 0.f, xg3 = 0.f;
        if (t < 256) {
            size_t base = ((size_t)pb * TT + step) * GG + (size_t)(rank * 64 + pj);
            xg0 = g_xg[base];
            xg1 = g_xg[base + 128];
            xg2 = g_xg[base + 256];
            xg3 = g_xg[base + 384];
        }

        // --- phase A: split-K partial dot products (4 rows per thread) ---
        float ax = 0.f, ay = 0.f, az = 0.f, aw = 0.f;
#pragma unroll
        for (int k = 0; k < 64; k++) {
            float4 hv = h4[k];           // broadcast LDS.128
            ax += w[k] * hv.x;
            ay += w[k] * hv.y;
            az += w[k] * hv.z;
            aw += w[k] * hv.w;
        }

        // --- route partials to the owning CTA ---
        if (!remote) {
            *(float4*)((char*)localDst + par * PAR_STRIDE) =
                make_float4(ax, ay, az, aw);
        } else {
            uint32_t a = remoteAddr + par * PAR_STRIDE;
            asm volatile("st.shared::cluster.f32 [%0], %1;" :: "r"(a),      "f"(ax) : "memory");
            asm volatile("st.shared::cluster.f32 [%0], %1;" :: "r"(a + 4),  "f"(ay) : "memory");
            asm volatile("st.shared::cluster.f32 [%0], %1;" :: "r"(a + 8),  "f"(az) : "memory");
            asm volatile("st.shared::cluster.f32 [%0], %1;" :: "r"(a + 12), "f"(aw) : "memory");
        }

        // cluster rendezvous: release my stores, acquire peer's
        asm volatile("barrier.cluster.arrive.aligned;" ::: "memory");
        asm volatile("barrier.cluster.wait.aligned;"   ::: "memory");

        // --- pointwise LSTM update for my owned (row, column) ---
        if (t < 256) {
            float gi = xg0 + pbuf[par][0][0][pj][pr] + pbuf[par][1][0][pj][pr];
            float gf = xg1 + pbuf[par][0][1][pj][pr] + pbuf[par][1][1][pj][pr];
            float gc = xg2 + pbuf[par][0][2][pj][pr] + pbuf[par][1][2][pj][pr];
            float go = xg3 + pbuf[par][0][3][pj][pr] + pbuf[par][1][3][pj][pr];

            float iv = fsigm(gi);
            float fv = fsigm(gf);
            float gv = ftanh(gc);
            float ov = fsigm(go);

            c = fv * c + iv * gv;
            float h = ov * ftanh(c);

            hbuf[pj][pr] = h;
            g_hs[((size_t)pb * TT + step) * HH + (size_t)(rank * 64 + pj)] = h;
        }
        __syncthreads();   // h visible to all 512 threads before next phase A
    }
}

// ---------------------------------------------------------------------------
// K3: out = hs @ W_out^T.  hs: [BT, 128], W_out: [64, 128].  (R3 verbatim)
// ---------------------------------------------------------------------------
__global__ __launch_bounds__(256) void k3_proj(
    const float* __restrict__ Wout,
    float* __restrict__ out)
{
    __shared__ __align__(16) float hs_s[32][128];   // 16 KB
    __shared__ __align__(16) float ws[128][64];     // 32 KB, [k][f] transposed

    const int bt0 = blockIdx.x * 32;
    const int t   = threadIdx.x;

    for (int i = t; i < 1024; i += 256) {
        int row = i >> 5;
        int q   = i & 31;
        ((float4*)hs_s[row])[q] =
            ((const float4*)(g_hs + (size_t)(bt0 + row) * HH))[q];
    }
    for (int i = t; i < 2048; i += 256) {
        int f  = i >> 5;
        int kq = i & 31;
        float4 v = ((const float4*)(Wout + (size_t)f * HH))[kq];
        int k = kq * 4;
        ws[k + 0][f] = v.x;
        ws[k + 1][f] = v.y;
        ws[k + 2][f] = v.z;
        ws[k + 3][f] = v.w;
    }
    __syncthreads();

    const int tf = t & 15;
    const int tr = t >> 4;

    float4 acc0 = make_float4(0.f, 0.f, 0.f, 0.f);
    float4 acc1 = make_float4(0.f, 0.f, 0.f, 0.f);

#pragma unroll
    for (int k = 0; k < 128; k++) {
        float4 w4 = *(float4*)&ws[k][tf * 4];
        float h0 = hs_s[tr][k];
        float h1 = hs_s[tr + 16][k];
        acc0.x += h0 * w4.x; acc0.y += h0 * w4.y;
        acc0.z += h0 * w4.z; acc0.w += h0 * w4.w;
        acc1.x += h1 * w4.x; acc1.y += h1 * w4.y;
        acc1.z += h1 * w4.z; acc1.w += h1 * w4.w;
    }

    *(float4*)(out + (size_t)(bt0 + tr) * FF + tf * 4)      = acc0;
    *(float4*)(out + (size_t)(bt0 + tr + 16) * FF + tf * 4) = acc1;
}

// ---------------------------------------------------------------------------
// launch
// ---------------------------------------------------------------------------
extern "C" void kernel_launch(void* const* d_in, const int* in_sizes, int n_in,
                              void* d_out, int out_size)
{
    const float* x    = (const float*)d_in[0];  // [256,1024,64]
    const float* Wih  = (const float*)d_in[1];  // [512,64]
    const float* Whh  = (const float*)d_in[2];  // [512,128]
    const float* bih  = (const float*)d_in[3];  // [512]
    const float* bhh  = (const float*)d_in[4];  // [512]
    const float* Wout = (const float*)d_in[5];  // [64,128]
    float* out = (float*)d_out;                 // [256,1024,64]

    (void)in_sizes; (void)n_in; (void)out_size;

    k1_xgemm<<<dim3((BB * TT) / 32, 4), 256>>>(x, Wih, bih, bhh);
    k2_lstm<<<128, 512>>>(Whh);
    k3_proj<<<(BB * TT) / 32, 256>>>(Wout, out);
}

// round 11
// speedup vs baseline: 1.3511x; 1.1201x over previous
#include <cuda_runtime.h>
#include <cuda_bf16.h>
#include <cstdint>
#include <cstddef>

// Problem constants
#define BB   256
#define TT   1024
#define FF   64
#define HH   128
#define GG   512   // 4*H

// ---------------------------------------------------------------------------
// Scratch (device globals; allocation in kernel_launch is forbidden)
// ---------------------------------------------------------------------------
__device__ float g_xg[(size_t)BB * TT * GG];   // 512 MB gate preactivations
__device__ float g_hs[(size_t)BB * TT * HH];   // 128 MB hidden states

// ---------------------------------------------------------------------------
// K1:  xg = x @ W_ih^T + (b_ih + b_hh)
//   Tile: 128 bt-rows x 32 gates, 256 threads, grid (2048, 16).
//   Thread = lane l (rows l, l+32, l+64, l+96) x warp w (gates 4w..4w+3).
//   Per k per warp: 1 uniform LDS.128 (w) + 4 conflict-free LDS.32 (x)
//   vs 16 FFMA  ->  FFMA-bound (register blocking = 16 MAC per x-load).
// ---------------------------------------------------------------------------
__global__ __launch_bounds__(256) void k1_xgemm(
    const float* __restrict__ x,
    const float* __restrict__ Wih,
    const float* __restrict__ bih,
    const float* __restrict__ bhh)
{
    __shared__ float xs[128][65];                 // bank = (row + k) % 32
    __shared__ __align__(16) float ws[64][32];    // [k][gate], 8 KB

    const int bt0 = blockIdx.x * 128;
    const int g0  = blockIdx.y * 32;
    const int t   = threadIdx.x;
    const int l   = t & 31;           // lane -> base row
    const int w   = t >> 5;           // warp -> 4-gate group
    const int gl  = w * 4;            // local gate base (warp-uniform)

    // load x tile coalesced (128 rows x 64 k = 2048 float4), scalar STS
    for (int i = t; i < 2048; i += 256) {
        int row = i >> 4;
        int kq  = i & 15;
        float4 v = ((const float4*)(x + (size_t)(bt0 + row) * FF))[kq];
        xs[row][kq * 4 + 0] = v.x;
        xs[row][kq * 4 + 1] = v.y;
        xs[row][kq * 4 + 2] = v.z;
        xs[row][kq * 4 + 3] = v.w;
    }
    // load W tile transposed (32 gates x 64 k = 512 float4)
    for (int i = t; i < 512; i += 256) {
        int g  = i >> 4;
        int kq = i & 15;
        float4 v = ((const float4*)(Wih + (size_t)(g0 + g) * FF))[kq];
        int k = kq * 4;
        ws[k + 0][g] = v.x;
        ws[k + 1][g] = v.y;
        ws[k + 2][g] = v.z;
        ws[k + 3][g] = v.w;
    }

    // bias for my 4 gates (same for all 4 rows)
    float4 bias;
    {
        float4 u = *(const float4*)(bih + g0 + gl);
        float4 v = *(const float4*)(bhh + g0 + gl);
        bias = make_float4(u.x + v.x, u.y + v.y, u.z + v.z, u.w + v.w);
    }
    float4 acc0 = bias, acc1 = bias, acc2 = bias, acc3 = bias;
    __syncthreads();

#pragma unroll 8
    for (int k = 0; k < 64; k++) {
        float4 wv = *(const float4*)&ws[k][gl];   // warp-uniform LDS.128
        float x0 = xs[l][k];                      // conflict-free LDS.32
        float x1 = xs[l + 32][k];
        float x2 = xs[l + 64][k];
        float x3 = xs[l + 96][k];
        acc0.x += x0 * wv.x; acc0.y += x0 * wv.y; acc0.z += x0 * wv.z; acc0.w += x0 * wv.w;
        acc1.x += x1 * wv.x; acc1.y += x1 * wv.y; acc1.z += x1 * wv.z; acc1.w += x1 * wv.w;
        acc2.x += x2 * wv.x; acc2.y += x2 * wv.y; acc2.z += x2 * wv.z; acc2.w += x2 * wv.w;
        acc3.x += x3 * wv.x; acc3.y += x3 * wv.y; acc3.z += x3 * wv.z; acc3.w += x3 * wv.w;
    }

    // store 4 gates for 4 rows (STG.128 each)
    const size_t gcol = (size_t)(g0 + gl);
    *(float4*)(g_xg + (size_t)(bt0 + l)      * GG + gcol) = acc0;
    *(float4*)(g_xg + (size_t)(bt0 + l + 32) * GG + gcol) = acc1;
    *(float4*)(g_xg + (size_t)(bt0 + l + 64) * GG + gcol) = acc2;
    *(float4*)(g_xg + (size_t)(bt0 + l + 96) * GG + gcol) = acc3;
}

// ---------------------------------------------------------------------------
// K2: persistent LSTM recurrence (measured-passing R8 variant):
//   64 clusters x 2 CTAs, scalar FFMA phase A, st.shared::cluster partials,
//   barrier.cluster rendezvous, fast MUFU pointwise.
// ---------------------------------------------------------------------------
__device__ __forceinline__ float fsigm(float v) {
    return __fdividef(1.0f, 1.0f + __expf(-v));
}
__device__ __forceinline__ float ftanh(float v) {
    // saturation-safe: no inf/inf
    return 1.0f - __fdividef(2.0f, 1.0f + __expf(2.0f * v));
}

__global__ __launch_bounds__(512, 1) __cluster_dims__(2, 1, 1)
void k2_lstm(const float* __restrict__ Whh)
{
    __shared__ __align__(16) float hbuf[64][4];            // my h-half, [kLocal][row]
    __shared__ __align__(16) float pbuf[2][2][4][64][4];   // [parity][src][gt][j][row]

    const int t    = threadIdx.x;          // == global gate index
    const int rank = blockIdx.x & 1;
    const int cid  = blockIdx.x >> 1;
    const int rowBase = cid * 4;
    const int kOff = rank * 64;

    // --- load my W_hh row-half into registers ---
    float w[64];
    {
        const float4* wp = (const float4*)(Whh + (size_t)t * HH + kOff);
#pragma unroll
        for (int q = 0; q < 16; q++) {
            float4 v = wp[q];
            w[4 * q + 0] = v.x;
            w[4 * q + 1] = v.y;
            w[4 * q + 2] = v.z;
            w[4 * q + 3] = v.w;
        }
    }

    // gate decomposition for partial routing
    const int gt    = t >> 7;        // gate type 0..3 (i,f,g,o)
    const int jg    = t & 127;       // h column of this gate
    const int owner = jg >> 6;       // owning CTA of that h column
    const int jl    = jg & 63;       // column local to owner
    const bool remote = (owner != rank);

    float* localDst = &pbuf[0][rank][gt][jl][0];
    uint32_t remoteAddr = 0;
    if (remote) {
        uint32_t la = (uint32_t)__cvta_generic_to_shared(localDst);
        asm volatile("mapa.shared::cluster.u32 %0, %1, %2;"
                     : "=r"(remoteAddr) : "r"(la), "r"(owner));
    }
    const uint32_t PAR_STRIDE = 2u * 4u * 64u * 4u * 4u;   // 8192 bytes

    // pointwise identity (first 256 threads): thread = (j, row)
    const int pj = t >> 2;
    const int pr = t & 3;
    const int pb = rowBase + pr;

    if (t < 256) hbuf[pj][pr] = 0.0f;
    float c = 0.0f;
    __syncthreads();

    const float4* h4 = (const float4*)hbuf;

    for (int step = 0; step < TT; step++) {
        const int par = step & 1;

        // prefetch this step's xg for my 4 owned gates (hidden under phase A)
        float xg0 = 0.f, xg1 = 0.f, xg2 = 0.f, xg3 = 0.f;
        if (t < 256) {
            size_t base = ((size_t)pb * TT + step) * GG + (size_t)(rank * 64 + pj);
            xg0 = g_xg[base];
            xg1 = g_xg[base + 128];
            xg2 = g_xg[base + 256];
            xg3 = g_xg[base + 384];
        }

        // --- phase A: split-K partial dot products (4 rows per thread) ---
        float ax = 0.f, ay = 0.f, az = 0.f, aw = 0.f;
#pragma unroll
        for (int k = 0; k < 64; k++) {
            float4 hv = h4[k];           // broadcast LDS.128
            ax += w[k] * hv.x;
            ay += w[k] * hv.y;
            az += w[k] * hv.z;
            aw += w[k] * hv.w;
        }

        // --- route partials to the owning CTA ---
        if (!remote) {
            *(float4*)((char*)localDst + par * PAR_STRIDE) =
                make_float4(ax, ay, az, aw);
        } else {
            uint32_t a = remoteAddr + par * PAR_STRIDE;
            asm volatile("st.shared::cluster.f32 [%0], %1;" :: "r"(a),      "f"(ax) : "memory");
            asm volatile("st.shared::cluster.f32 [%0], %1;" :: "r"(a + 4),  "f"(ay) : "memory");
            asm volatile("st.shared::cluster.f32 [%0], %1;" :: "r"(a + 8),  "f"(az) : "memory");
            asm volatile("st.shared::cluster.f32 [%0], %1;" :: "r"(a + 12), "f"(aw) : "memory");
        }

        // cluster rendezvous: release my stores, acquire peer's
        asm volatile("barrier.cluster.arrive.aligned;" ::: "memory");
        asm volatile("barrier.cluster.wait.aligned;"   ::: "memory");

        // --- pointwise LSTM update for my owned (row, column) ---
        if (t < 256) {
            float gi = xg0 + pbuf[par][0][0][pj][pr] + pbuf[par][1][0][pj][pr];
            float gf = xg1 + pbuf[par][0][1][pj][pr] + pbuf[par][1][1][pj][pr];
            float gc = xg2 + pbuf[par][0][2][pj][pr] + pbuf[par][1][2][pj][pr];
            float go = xg3 + pbuf[par][0][3][pj][pr] + pbuf[par][1][3][pj][pr];

            float iv = fsigm(gi);
            float fv = fsigm(gf);
            float gv = ftanh(gc);
            float ov = fsigm(go);

            c = fv * c + iv * gv;
            float h = ov * ftanh(c);

            hbuf[pj][pr] = h;
            g_hs[((size_t)pb * TT + step) * HH + (size_t)(rank * 64 + pj)] = h;
        }
        __syncthreads();   // h visible to all 512 threads before next phase A
    }
}

// ---------------------------------------------------------------------------
// K3: out = hs @ W_out^T.  hs: [BT, 128], W_out: [64, 128].  (R3 verbatim)
// ---------------------------------------------------------------------------
__global__ __launch_bounds__(256) void k3_proj(
    const float* __restrict__ Wout,
    float* __restrict__ out)
{
    __shared__ __align__(16) float hs_s[32][128];   // 16 KB
    __shared__ __align__(16) float ws[128][64];     // 32 KB, [k][f] transposed

    const int bt0 = blockIdx.x * 32;
    const int t   = threadIdx.x;

    for (int i = t; i < 1024; i += 256) {
        int row = i >> 5;
        int q   = i & 31;
        ((float4*)hs_s[row])[q] =
            ((const float4*)(g_hs + (size_t)(bt0 + row) * HH))[q];
    }
    for (int i = t; i < 2048; i += 256) {
        int f  = i >> 5;
        int kq = i & 31;
        float4 v = ((const float4*)(Wout + (size_t)f * HH))[kq];
        int k = kq * 4;
        ws[k + 0][f] = v.x;
        ws[k + 1][f] = v.y;
        ws[k + 2][f] = v.z;
        ws[k + 3][f] = v.w;
    }
    __syncthreads();

    const int tf = t & 15;
    const int tr = t >> 4;

    float4 acc0 = make_float4(0.f, 0.f, 0.f, 0.f);
    float4 acc1 = make_float4(0.f, 0.f, 0.f, 0.f);

#pragma unroll
    for (int k = 0; k < 128; k++) {
        float4 w4 = *(float4*)&ws[k][tf * 4];
        float h0 = hs_s[tr][k];
        float h1 = hs_s[tr + 16][k];
        acc0.x += h0 * w4.x; acc0.y += h0 * w4.y;
        acc0.z += h0 * w4.z; acc0.w += h0 * w4.w;
        acc1.x += h1 * w4.x; acc1.y += h1 * w4.y;
        acc1.z += h1 * w4.z; acc1.w += h1 * w4.w;
    }

    *(float4*)(out + (size_t)(bt0 + tr) * FF + tf * 4)      = acc0;
    *(float4*)(out + (size_t)(bt0 + tr + 16) * FF + tf * 4) = acc1;
}

// ---------------------------------------------------------------------------
// launch
// ---------------------------------------------------------------------------
extern "C" void kernel_launch(void* const* d_in, const int* in_sizes, int n_in,
                              void* d_out, int out_size)
{
    const float* x    = (const float*)d_in[0];  // [256,1024,64]
    const float* Wih  = (const float*)d_in[1];  // [512,64]
    const float* Whh  = (const float*)d_in[2];  // [512,128]
    const float* bih  = (const float*)d_in[3];  // [512]
    const float* bhh  = (const float*)d_in[4];  // [512]
    const float* Wout = (const float*)d_in[5];  // [64,128]
    float* out = (float*)d_out;                 // [256,1024,64]

    (void)in_sizes; (void)n_in; (void)out_size;

    k1_xgemm<<<dim3((BB * TT) / 128, 16), 256>>>(x, Wih, bih, bhh);
    k2_lstm<<<128, 512>>>(Whh);
    k3_proj<<<(BB * TT) / 32, 256>>>(Wout, out);
}

// round 12
// speedup vs baseline: 1.4987x; 1.1092x over previous
#include <cuda_runtime.h>
#include <cuda_bf16.h>
#include <cstdint>
#include <cstddef>

// Problem constants
#define BB   256
#define TT   1024
#define FF   64
#define HH   128
#define GG   512   // 4*H

using u64 = unsigned long long;

// ---------------------------------------------------------------------------
// Scratch (device globals; allocation in kernel_launch is forbidden)
// ---------------------------------------------------------------------------
__device__ float g_xg[(size_t)BB * TT * GG];   // 512 MB gate preactivations
__device__ float g_hs[(size_t)BB * TT * HH];   // 128 MB hidden states

// ---------------------------------------------------------------------------
// K1:  xg = x @ W_ih^T + (b_ih + b_hh)
//   Tile: 128 bt-rows x 64 gates, 256 threads, grid (2048, 8).
//   Thread = lane l (rows l,+32,+64,+96) x warp w (gates 8w..8w+7).
//   Per k per warp: 2 uniform LDS.128 + 4 LDS.32 vs 32 FFMA (ratio 5.3).
//   xs stored rotation-swizzled: col=(k+row)&63 -> conflict-free, no padding
//   (exactly 48 KB static smem with ws).
// ---------------------------------------------------------------------------
__global__ __launch_bounds__(256) void k1_xgemm(
    const float* __restrict__ x,
    const float* __restrict__ Wih,
    const float* __restrict__ bih,
    const float* __restrict__ bhh)
{
    __shared__ float xs[128][64];                 // [row][(k+row)&63], 32 KB
    __shared__ __align__(16) float ws[64][64];    // [k][gate], 16 KB

    const int bt0 = blockIdx.x * 128;
    const int g0  = blockIdx.y * 64;
    const int t   = threadIdx.x;
    const int l   = t & 31;           // lane -> base row
    const int w   = t >> 5;           // warp -> 8-gate group
    const int gl  = w * 8;            // local gate base (warp-uniform)

    // load x tile coalesced (128 rows x 64 k = 2048 float4), rotation store
    for (int i = t; i < 2048; i += 256) {
        int row = i >> 4;
        int kq  = i & 15;
        float4 v = ((const float4*)(x + (size_t)(bt0 + row) * FF))[kq];
        int k = kq * 4;
        xs[row][(k + 0 + row) & 63] = v.x;
        xs[row][(k + 1 + row) & 63] = v.y;
        xs[row][(k + 2 + row) & 63] = v.z;
        xs[row][(k + 3 + row) & 63] = v.w;
    }
    // load W tile transposed (64 gates x 64 k = 1024 float4)
    for (int i = t; i < 1024; i += 256) {
        int g  = i >> 4;
        int kq = i & 15;
        float4 v = ((const float4*)(Wih + (size_t)(g0 + g) * FF))[kq];
        int k = kq * 4;
        ws[k + 0][g] = v.x;
        ws[k + 1][g] = v.y;
        ws[k + 2][g] = v.z;
        ws[k + 3][g] = v.w;
    }

    // bias for my 8 gates (same for all 4 rows)
    float4 ba, bb;
    {
        float4 u = *(const float4*)(bih + g0 + gl);
        float4 v = *(const float4*)(bhh + g0 + gl);
        ba = make_float4(u.x + v.x, u.y + v.y, u.z + v.z, u.w + v.w);
        u = *(const float4*)(bih + g0 + gl + 4);
        v = *(const float4*)(bhh + g0 + gl + 4);
        bb = make_float4(u.x + v.x, u.y + v.y, u.z + v.z, u.w + v.w);
    }
    // acc[r*2+q]: row r, gate-quad q
    float4 acc[8];
#pragma unroll
    for (int r = 0; r < 4; r++) { acc[r * 2] = ba; acc[r * 2 + 1] = bb; }
    __syncthreads();

#pragma unroll 4
    for (int k = 0; k < 64; k++) {
        float4 wa = *(const float4*)&ws[k][gl];       // warp-uniform LDS.128
        float4 wb = *(const float4*)&ws[k][gl + 4];
        float xv[4];
        xv[0] = xs[l][(k + l) & 63];                  // conflict-free LDS.32
        xv[1] = xs[l + 32][(k + l + 32) & 63];
        xv[2] = xs[l + 64][(k + l + 64) & 63];
        xv[3] = xs[l + 96][(k + l + 96) & 63];
#pragma unroll
        for (int r = 0; r < 4; r++) {
            float xr = xv[r];
            acc[r*2].x   += xr * wa.x; acc[r*2].y   += xr * wa.y;
            acc[r*2].z   += xr * wa.z; acc[r*2].w   += xr * wa.w;
            acc[r*2+1].x += xr * wb.x; acc[r*2+1].y += xr * wb.y;
            acc[r*2+1].z += xr * wb.z; acc[r*2+1].w += xr * wb.w;
        }
    }

    // store 8 gates for 4 rows (2x STG.128 per row)
    const size_t gcol = (size_t)(g0 + gl);
#pragma unroll
    for (int r = 0; r < 4; r++) {
        float* outp = g_xg + (size_t)(bt0 + l + 32 * r) * GG + gcol;
        *(float4*)(outp)     = acc[r * 2];
        *(float4*)(outp + 4) = acc[r * 2 + 1];
    }
}

// ---------------------------------------------------------------------------
// K2: persistent LSTM recurrence, 64 clusters x 2 CTAs, TWO row-groups per
//   cluster pipelined against the two barrier.cluster phases per step:
//     A(g0) route0 sync arrive | A(g1) route1 wait sync arrive |
//     pw(g0 by t<128) wait | pw(g1 by t in [128,256)) sync
//   pbuf for g0 is parity double-buffered (route0(t+1) races peer pw0(t));
//   pbuf g1 single-buffered (provably ordered). Scalar FFMA + MUFU pointwise.
// ---------------------------------------------------------------------------
__device__ __forceinline__ float fsigm(float v) {
    return __fdividef(1.0f, 1.0f + __expf(-v));
}
__device__ __forceinline__ float ftanh(float v) {
    return 1.0f - __fdividef(2.0f, 1.0f + __expf(2.0f * v));
}

__global__ __launch_bounds__(512, 1) __cluster_dims__(2, 1, 1)
void k2_lstm(const float* __restrict__ Whh)
{
    __shared__ __align__(16) float hbuf[2][64][2];           // [grp][kLocal][row]
    __shared__ __align__(16) float pbuf0[2][2][4][64][2];    // [par][src][gt][j][row] 8KB
    __shared__ __align__(16) float pbuf1[2][4][64][2];       //      [src][gt][j][row] 4KB

    const int t    = threadIdx.x;          // == global gate index
    const int rank = blockIdx.x & 1;
    const int cid  = blockIdx.x >> 1;
    const int rowBase = cid * 4;
    const int kOff = rank * 64;

    // --- load my W_hh row-half into registers ---
    float w[64];
    {
        const float4* wp = (const float4*)(Whh + (size_t)t * HH + kOff);
#pragma unroll
        for (int q = 0; q < 16; q++) {
            float4 v = wp[q];
            w[4 * q + 0] = v.x;
            w[4 * q + 1] = v.y;
            w[4 * q + 2] = v.z;
            w[4 * q + 3] = v.w;
        }
    }

    // gate decomposition for partial routing
    const int gt    = t >> 7;        // gate type 0..3 (i,f,g,o)
    const int jg    = t & 127;       // h column of this gate
    const int owner = jg >> 6;       // owning CTA of that h column
    const int jl    = jg & 63;       // column local to owner
    const bool remote = (owner != rank);

    float* dst0 = &pbuf0[0][rank][gt][jl][0];
    float* dst1 = &pbuf1[rank][gt][jl][0];
    uint32_t rAddr0 = 0, rAddr1 = 0;
    if (remote) {
        uint32_t la0 = (uint32_t)__cvta_generic_to_shared(dst0);
        uint32_t la1 = (uint32_t)__cvta_generic_to_shared(dst1);
        asm volatile("mapa.shared::cluster.u32 %0, %1, %2;"
                     : "=r"(rAddr0) : "r"(la0), "r"(owner));
        asm volatile("mapa.shared::cluster.u32 %0, %1, %2;"
                     : "=r"(rAddr1) : "r"(la1), "r"(owner));
    }
    const uint32_t PAR0_STRIDE = 2u * 4u * 64u * 2u * 4u;   // 4096 B (pbuf0 parity)

    // pointwise identity (t < 256): grp = t>>7, item u = t&127 -> (pj, pr)
    const int pgrp = (t >> 7) & 1;
    const int pu   = t & 127;
    const int pj   = pu >> 1;        // owned h column (local)
    const int pr   = pu & 1;         // row within group
    const int pb   = rowBase + 2 * pgrp + pr;   // global batch row

    if (t < 256) hbuf[pgrp][pj][pr] = 0.0f;
    float c = 0.0f;
    __syncthreads();

    for (int step = 0; step < TT; step++) {
        const int par = step & 1;

        // prefetch this step's xg for my 4 owned gates (hidden under phase A)
        float xg0 = 0.f, xg1 = 0.f, xg2 = 0.f, xg3 = 0.f;
        if (t < 256) {
            size_t base = ((size_t)pb * TT + step) * GG + (size_t)(rank * 64 + pj);
            xg0 = g_xg[base];
            xg1 = g_xg[base + 128];
            xg2 = g_xg[base + 256];
            xg3 = g_xg[base + 384];
        }

        // --- A(g0): 2-row split-K dot products ---
        float a0 = 0.f, a1 = 0.f;
#pragma unroll
        for (int k = 0; k < 64; k++) {
            float2 hv = *(const float2*)&hbuf[0][k][0];   // broadcast LDS.64
            a0 += w[k] * hv.x;
            a1 += w[k] * hv.y;
        }
        if (!remote) {
            *(float2*)((char*)dst0 + par * PAR0_STRIDE) = make_float2(a0, a1);
        } else {
            uint32_t a = rAddr0 + par * PAR0_STRIDE;
            asm volatile("st.shared::cluster.f32 [%0], %1;" :: "r"(a),     "f"(a0) : "memory");
            asm volatile("st.shared::cluster.f32 [%0], %1;" :: "r"(a + 4), "f"(a1) : "memory");
        }
        __syncthreads();                                   // local pbuf0 visible
        asm volatile("barrier.cluster.arrive.aligned;" ::: "memory");   // phase p

        // --- A(g1) (hides phase-p release latency) ---
        float b0 = 0.f, b1 = 0.f;
#pragma unroll
        for (int k = 0; k < 64; k++) {
            float2 hv = *(const float2*)&hbuf[1][k][0];
            b0 += w[k] * hv.x;
            b1 += w[k] * hv.y;
        }
        if (!remote) {
            *(float2*)dst1 = make_float2(b0, b1);
        } else {
            asm volatile("st.shared::cluster.f32 [%0], %1;" :: "r"(rAddr1),     "f"(b0) : "memory");
            asm volatile("st.shared::cluster.f32 [%0], %1;" :: "r"(rAddr1 + 4), "f"(b1) : "memory");
        }
        asm volatile("barrier.cluster.wait.aligned;" ::: "memory");     // p: peer pbuf0 ready
        __syncthreads();                                   // local pbuf1 visible
        asm volatile("barrier.cluster.arrive.aligned;" ::: "memory");   // phase p+1

        // --- pw(g0) by threads 0..127 (overlaps phase-(p+1) release) ---
        if (t < 128) {
            const float (*pb0)[4][64][2] = &pbuf0[par][0];
            float gi = xg0 + pb0[0][0][pj][pr] + pb0[1][0][pj][pr];
            float gf = xg1 + pb0[0][1][pj][pr] + pb0[1][1][pj][pr];
            float gc = xg2 + pb0[0][2][pj][pr] + pb0[1][2][pj][pr];
            float go = xg3 + pb0[0][3][pj][pr] + pb0[1][3][pj][pr];
            float iv = fsigm(gi), fv = fsigm(gf), gv = ftanh(gc), ov = fsigm(go);
            c = fv * c + iv * gv;
            float h = ov * ftanh(c);
            hbuf[0][pj][pr] = h;
            g_hs[((size_t)pb * TT + step) * HH + (size_t)(rank * 64 + pj)] = h;
        }
        asm volatile("barrier.cluster.wait.aligned;" ::: "memory");     // p+1: peer pbuf1 ready

        // --- pw(g1) by threads 128..255 ---
        if (t >= 128 && t < 256) {
            float gi = xg0 + pbuf1[0][0][pj][pr] + pbuf1[1][0][pj][pr];
            float gf = xg1 + pbuf1[0][1][pj][pr] + pbuf1[1][1][pj][pr];
            float gc = xg2 + pbuf1[0][2][pj][pr] + pbuf1[1][2][pj][pr];
            float go = xg3 + pbuf1[0][3][pj][pr] + pbuf1[1][3][pj][pr];
            float iv = fsigm(gi), fv = fsigm(gf), gv = ftanh(gc), ov = fsigm(go);
            c = fv * c + iv * gv;
            float h = ov * ftanh(c);
            hbuf[1][pj][pr] = h;
            g_hs[((size_t)pb * TT + step) * HH + (size_t)(rank * 64 + pj)] = h;
        }
        __syncthreads();   // h (both groups) visible before next phase A
    }
}

// ---------------------------------------------------------------------------
// K3: out = hs @ W_out^T.  hs: [BT, 128], W_out: [64, 128].  (R3 verbatim)
// ---------------------------------------------------------------------------
__global__ __launch_bounds__(256) void k3_proj(
    const float* __restrict__ Wout,
    float* __restrict__ out)
{
    __shared__ __align__(16) float hs_s[32][128];   // 16 KB
    __shared__ __align__(16) float ws[128][64];     // 32 KB, [k][f] transposed

    const int bt0 = blockIdx.x * 32;
    const int t   = threadIdx.x;

    for (int i = t; i < 1024; i += 256) {
        int row = i >> 5;
        int q   = i & 31;
        ((float4*)hs_s[row])[q] =
            ((const float4*)(g_hs + (size_t)(bt0 + row) * HH))[q];
    }
    for (int i = t; i < 2048; i += 256) {
        int f  = i >> 5;
        int kq = i & 31;
        float4 v = ((const float4*)(Wout + (size_t)f * HH))[kq];
        int k = kq * 4;
        ws[k + 0][f] = v.x;
        ws[k + 1][f] = v.y;
        ws[k + 2][f] = v.z;
        ws[k + 3][f] = v.w;
    }
    __syncthreads();

    const int tf = t & 15;
    const int tr = t >> 4;

    float4 acc0 = make_float4(0.f, 0.f, 0.f, 0.f);
    float4 acc1 = make_float4(0.f, 0.f, 0.f, 0.f);

#pragma unroll
    for (int k = 0; k < 128; k++) {
        float4 w4 = *(float4*)&ws[k][tf * 4];
        float h0 = hs_s[tr][k];
        float h1 = hs_s[tr + 16][k];
        acc0.x += h0 * w4.x; acc0.y += h0 * w4.y;
        acc0.z += h0 * w4.z; acc0.w += h0 * w4.w;
        acc1.x += h1 * w4.x; acc1.y += h1 * w4.y;
        acc1.z += h1 * w4.z; acc1.w += h1 * w4.w;
    }

    *(float4*)(out + (size_t)(bt0 + tr) * FF + tf * 4)      = acc0;
    *(float4*)(out + (size_t)(bt0 + tr + 16) * FF + tf * 4) = acc1;
}

// ---------------------------------------------------------------------------
// launch
// ---------------------------------------------------------------------------
extern "C" void kernel_launch(void* const* d_in, const int* in_sizes, int n_in,
                              void* d_out, int out_size)
{
    const float* x    = (const float*)d_in[0];  // [256,1024,64]
    const float* Wih  = (const float*)d_in[1];  // [512,64]
    const float* Whh  = (const float*)d_in[2];  // [512,128]
    const float* bih  = (const float*)d_in[3];  // [512]
    const float* bhh  = (const float*)d_in[4];  // [512]
    const float* Wout = (const float*)d_in[5];  // [64,128]
    float* out = (float*)d_out;                 // [256,1024,64]

    (void)in_sizes; (void)n_in; (void)out_size;

    k1_xgemm<<<dim3((BB * TT) / 128, 8), 256>>>(x, Wih, bih, bhh);
    k2_lstm<<<128, 512>>>(Whh);
    k3_proj<<<(BB * TT) / 32, 256>>>(Wout, out);
}